// round 1
// baseline (speedup 1.0000x reference)
#include <cuda_runtime.h>
#include <math.h>

// ---------------------------------------------------------------------------
// Fused: features -> MLP (Linear/SiLU/Linear) -> gated tensor readout ->
//        symmetrize -> frame rotation -> sorted segment-sum pooling.
//
// Block = 64 nodes, 256 threads. All fp32.
// ---------------------------------------------------------------------------

#define MTILE 64
#define NTHREADS 256

// smem layout (float offsets). Total 37120 floats = 148480 bytes.
#define FEAT_PITCH 68                 // 64 + pad, 16B-aligned rows
#define OFF_FEAT   0                  // featT[320][68]  -> 21760 floats
#define OFF_W1S    21760              // W1 chunk [32][160] -> 5120 floats
#define OFF_W2S    26880              // W2 [160][64] -> 10240 floats (end 37120)
#define OFF_HT     0                  // hT[160][68] reuses FEAT (10880 floats)
#define OFF_ALPHA  21760              // alpha[64][65] reuses W1S (4160 floats)
#define OFF_GS     25920              // Gs[64][9] (576 floats) still inside W1S region
#define SMEM_FLOATS 37120
#define SMEM_BYTES  (SMEM_FLOATS * 4)

__global__ void __launch_bounds__(NTHREADS)
tensor_message_fused(const float* __restrict__ h,
                     const float* __restrict__ v,
                     const float* __restrict__ t,
                     const float* __restrict__ frames,
                     const int* __restrict__ batch,
                     const float* __restrict__ W1,
                     const float* __restrict__ b1,
                     const float* __restrict__ W2,
                     const float* __restrict__ b2,
                     float* __restrict__ out,
                     int N, int num_graphs)
{
    extern __shared__ float s[];
    const int tid = threadIdx.x;
    const int m0  = blockIdx.x * MTILE;
    const int mlim = (N - m0 < MTILE) ? (N - m0) : MTILE;

    // ---- stage W2 (lives whole block) ----
    for (int i = tid; i < 160 * 64; i += NTHREADS)
        s[OFF_W2S + i] = W2[i];

    // ---- features: h channels 0..127 ----
    for (int i = tid; i < MTILE * 128; i += NTHREADS) {
        int m = i >> 7, k = i & 127;
        float val = 0.0f;
        if (m < mlim) val = h[(size_t)(m0 + m) * 128 + k];
        s[OFF_FEAT + k * FEAT_PITCH + m] = val;
    }
    // ---- v norms: channels 128..191 ----
    for (int i = tid; i < MTILE * 64; i += NTHREADS) {
        int m = i >> 6, j = i & 63;
        float val = 0.0f;
        if (m < mlim) {
            const float* vp = v + ((size_t)(m0 + m) * 64 + j) * 3;
            float x = vp[0], y = vp[1], z = vp[2];
            val = sqrtf(x * x + y * y + z * z);
        }
        s[OFF_FEAT + (128 + j) * FEAT_PITCH + m] = val;
    }
    // ---- t invariants (trace, frob): channels 192..319 ----
    for (int i = tid; i < MTILE * 64; i += NTHREADS) {
        int m = i >> 6, c = i & 63;
        float tr = 0.0f, fb = 0.0f;
        if (m < mlim) {
            const float* tp = t + ((size_t)(m0 + m) * 64 + c) * 9;
            float q0 = tp[0], q1 = tp[1], q2 = tp[2];
            float q3 = tp[3], q4 = tp[4], q5 = tp[5];
            float q6 = tp[6], q7 = tp[7], q8 = tp[8];
            tr = q0 + q4 + q8;
            fb = sqrtf(q0*q0 + q1*q1 + q2*q2 + q3*q3 + q4*q4 +
                       q5*q5 + q6*q6 + q7*q7 + q8*q8);
        }
        s[OFF_FEAT + (192 + 2 * c) * FEAT_PITCH + m] = tr;
        s[OFF_FEAT + (193 + 2 * c) * FEAT_PITCH + m] = fb;
    }
    __syncthreads();

    // ======================= GEMM1: [64,320] @ [320,160] ====================
    const int tm  = (tid & 15) * 4;    // 4 node-rows
    const int tn  = (tid >> 4) * 10;   // 10 hidden cols

    float acc[4][10];
#pragma unroll
    for (int i = 0; i < 4; ++i)
#pragma unroll
        for (int j = 0; j < 10; ++j) acc[i][j] = 0.0f;

    for (int kc = 0; kc < 320; kc += 32) {
        for (int i = tid; i < 32 * 160; i += NTHREADS)
            s[OFF_W1S + i] = W1[(size_t)kc * 160 + i];
        __syncthreads();

#pragma unroll 4
        for (int k = 0; k < 32; ++k) {
            const float4 a4 = *reinterpret_cast<const float4*>(
                &s[OFF_FEAT + (kc + k) * FEAT_PITCH + tm]);
            float av[4] = {a4.x, a4.y, a4.z, a4.w};
            float bv[10];
#pragma unroll
            for (int j = 0; j < 10; j += 2) {
                const float2 bb = *reinterpret_cast<const float2*>(
                    &s[OFF_W1S + k * 160 + tn + j]);
                bv[j] = bb.x; bv[j + 1] = bb.y;
            }
#pragma unroll
            for (int i = 0; i < 4; ++i)
#pragma unroll
                for (int j = 0; j < 10; ++j)
                    acc[i][j] = fmaf(av[i], bv[j], acc[i][j]);
        }
        __syncthreads();
    }

    // bias + SiLU, write hT (reuses FEAT region; sync above guarantees done)
#pragma unroll
    for (int j = 0; j < 10; ++j) {
        const float bj = b1[tn + j];
#pragma unroll
        for (int i = 0; i < 4; ++i) {
            float x  = acc[i][j] + bj;
            float sg = 1.0f / (1.0f + expf(-x));
            s[OFF_HT + (tn + j) * FEAT_PITCH + tm + i] = x * sg;
        }
    }
    __syncthreads();

    // ======================= GEMM2: [64,160] @ [160,64] =====================
    const int tn2 = (tid >> 4) * 4;
    float acc2[4][4];
#pragma unroll
    for (int i = 0; i < 4; ++i)
#pragma unroll
        for (int j = 0; j < 4; ++j) acc2[i][j] = 0.0f;

#pragma unroll 4
    for (int k = 0; k < 160; ++k) {
        const float4 a4 = *reinterpret_cast<const float4*>(
            &s[OFF_HT + k * FEAT_PITCH + tm]);
        const float4 b4 = *reinterpret_cast<const float4*>(
            &s[OFF_W2S + k * 64 + tn2]);
        float av[4] = {a4.x, a4.y, a4.z, a4.w};
        float bv[4] = {b4.x, b4.y, b4.z, b4.w};
#pragma unroll
        for (int i = 0; i < 4; ++i)
#pragma unroll
            for (int j = 0; j < 4; ++j)
                acc2[i][j] = fmaf(av[i], bv[j], acc2[i][j]);
    }

    // alphas -> smem (ALPHA region reuses W1S; nobody reads W1S anymore)
#pragma unroll
    for (int j = 0; j < 4; ++j) {
        const float bj = b2[tn2 + j];
#pragma unroll
        for (int i = 0; i < 4; ++i)
            s[OFF_ALPHA + (tm + i) * 65 + tn2 + j] = acc2[i][j] + bj;
    }
    __syncthreads();

    // ================ epilogue: gated sum, symmetrize, rotate ===============
    const int node = tid >> 2;   // 0..63
    const int jj   = tid & 3;    // 16 channels each
    float g[9];
#pragma unroll
    for (int k = 0; k < 9; ++k) g[k] = 0.0f;

    if (node < mlim) {
        const float4* tp4 = reinterpret_cast<const float4*>(
            t + ((size_t)(m0 + node) * 64 + jj * 16) * 9);
        const float* ap = &s[OFF_ALPHA + node * 65 + jj * 16];
#pragma unroll
        for (int cb = 0; cb < 4; ++cb) {
            float4 q[9];
#pragma unroll
            for (int u = 0; u < 9; ++u) q[u] = tp4[cb * 9 + u];
            const float* f = reinterpret_cast<const float*>(q);
            float al[4];
#pragma unroll
            for (int c = 0; c < 4; ++c) al[c] = ap[cb * 4 + c];
#pragma unroll
            for (int c = 0; c < 4; ++c)
#pragma unroll
                for (int k = 0; k < 9; ++k)
                    g[k] = fmaf(al[c], f[c * 9 + k], g[k]);
        }
    }

    // reduce across the 4 lanes of this node (contiguous lanes)
#pragma unroll
    for (int k = 0; k < 9; ++k) {
        g[k] += __shfl_xor_sync(0xFFFFFFFFu, g[k], 1);
        g[k] += __shfl_xor_sync(0xFFFFFFFFu, g[k], 2);
    }

    if (jj == 0) {
        float G[9];
        if (node < mlim) {
            float S[9];
#pragma unroll
            for (int a = 0; a < 3; ++a)
#pragma unroll
                for (int b = 0; b < 3; ++b)
                    S[a * 3 + b] = 0.5f * (g[a * 3 + b] + g[b * 3 + a]);
            const float* rp = frames + (size_t)(m0 + node) * 9;
            float R[9];
#pragma unroll
            for (int k = 0; k < 9; ++k) R[k] = rp[k];
            float P[9];
#pragma unroll
            for (int a = 0; a < 3; ++a)
#pragma unroll
                for (int c = 0; c < 3; ++c)
                    P[a * 3 + c] = R[a * 3 + 0] * S[0 * 3 + c]
                                 + R[a * 3 + 1] * S[1 * 3 + c]
                                 + R[a * 3 + 2] * S[2 * 3 + c];
#pragma unroll
            for (int a = 0; a < 3; ++a)
#pragma unroll
                for (int d = 0; d < 3; ++d)
                    G[a * 3 + d] = P[a * 3 + 0] * R[d * 3 + 0]
                                 + P[a * 3 + 1] * R[d * 3 + 1]
                                 + P[a * 3 + 2] * R[d * 3 + 2];
        } else {
#pragma unroll
            for (int k = 0; k < 9; ++k) G[k] = 0.0f;
        }
#pragma unroll
        for (int k = 0; k < 9; ++k) s[OFF_GS + node * 9 + k] = G[k];
    }
    __syncthreads();

    // ============ sorted-run segment sum: few atomics per block =============
    if (tid < 9) {
        int cur = batch[m0];
        float run = 0.0f;
        for (int n = 0; n < mlim; ++n) {
            int b = batch[m0 + n];
            if (b != cur) {
                if ((unsigned)cur < (unsigned)num_graphs)
                    atomicAdd(&out[(size_t)cur * 9 + tid], run);
                run = 0.0f;
                cur = b;
            }
            run += s[OFF_GS + n * 9 + tid];
        }
        if ((unsigned)cur < (unsigned)num_graphs)
            atomicAdd(&out[(size_t)cur * 9 + tid], run);
    }
}

extern "C" void kernel_launch(void* const* d_in, const int* in_sizes, int n_in,
                              void* d_out, int out_size)
{
    const float* h      = (const float*)d_in[0];
    const float* v      = (const float*)d_in[1];
    const float* t      = (const float*)d_in[2];
    const float* frames = (const float*)d_in[3];
    const int*   batch  = (const int*)d_in[4];   // JAX default: int64 request demotes to int32
    const float* W1     = (const float*)d_in[5];
    const float* b1     = (const float*)d_in[6];
    const float* W2     = (const float*)d_in[7];
    const float* b2     = (const float*)d_in[8];
    float* out = (float*)d_out;

    const int N = in_sizes[0] / 128;          // h is [N,128]
    const int num_graphs = out_size / 9;

    cudaMemsetAsync(d_out, 0, (size_t)out_size * sizeof(float));

    cudaFuncSetAttribute(tensor_message_fused,
                         cudaFuncAttributeMaxDynamicSharedMemorySize, SMEM_BYTES);

    const int grid = (N + MTILE - 1) / MTILE;
    tensor_message_fused<<<grid, NTHREADS, SMEM_BYTES>>>(
        h, v, t, frames, batch, W1, b1, W2, b2, out, N, num_graphs);
}

// round 2
// speedup vs baseline: 1.8416x; 1.8416x over previous
#include <cuda_runtime.h>
#include <math.h>

// ---------------------------------------------------------------------------
// Fused: features -> MLP (Linear/SiLU/Linear) -> gated tensor readout ->
//        symmetrize -> frame rotation -> sorted segment-sum pooling.
//
// Round 2: occupancy fix. Features built in K-chunks (no 87KB featT stage),
// W2 read through L1 (no 40KB stage). smem high-water 43.5KB -> 3 CTAs/SM.
// ---------------------------------------------------------------------------

#define MTILE 64
#define NTHREADS 256
#define FEAT_PITCH 68

// smem float offsets (regions overlaid across phases, separated by barriers)
#define OFF_FEAT   0        // feat chunk [32][68]   -> 2176 floats
#define OFF_W1S    2176     // W1 chunk  [32][160]  -> 5120 floats (end 7296)
#define OFF_HT     0        // hT [160][68]         -> 10880 floats (phase 2)
#define OFF_ALPHA  0        // alpha [64][65]       -> 4160 floats (phase 3)
#define OFF_GS     4352     // Gs [64][9]           -> 576 floats  (phase 4)
#define SMEM_FLOATS 10880
#define SMEM_BYTES  (SMEM_FLOATS * 4)

__global__ void __launch_bounds__(NTHREADS, 3)
tensor_message_fused(const float* __restrict__ h,
                     const float* __restrict__ v,
                     const float* __restrict__ t,
                     const float* __restrict__ frames,
                     const int* __restrict__ batch,
                     const float* __restrict__ W1,
                     const float* __restrict__ b1,
                     const float* __restrict__ W2,
                     const float* __restrict__ b2,
                     float* __restrict__ out,
                     int N, int num_graphs)
{
    extern __shared__ float s[];
    const int tid = threadIdx.x;
    const int m0  = blockIdx.x * MTILE;
    const int mlim = (N - m0 < MTILE) ? (N - m0) : MTILE;

    // ======================= GEMM1: [64,320] @ [320,160] ====================
    const int tm  = (tid & 15) * 4;    // 4 node-rows
    const int tn  = (tid >> 4) * 10;   // 10 hidden cols

    float acc[4][10];
#pragma unroll
    for (int i = 0; i < 4; ++i)
#pragma unroll
        for (int j = 0; j < 10; ++j) acc[i][j] = 0.0f;

    for (int kc = 0; kc < 320; kc += 32) {
        // ---- build feature chunk [32 k-rows][64 nodes] ----
        if (kc < 128) {
            // h channels kc..kc+31
            for (int i = tid; i < MTILE * 32; i += NTHREADS) {
                int m = i >> 5, k = i & 31;
                float val = 0.0f;
                if (m < mlim) val = h[(size_t)(m0 + m) * 128 + kc + k];
                s[OFF_FEAT + k * FEAT_PITCH + m] = val;
            }
        } else if (kc < 192) {
            // v-norm channels
            const int j0 = kc - 128;
            for (int i = tid; i < MTILE * 32; i += NTHREADS) {
                int m = i >> 5, k = i & 31;
                float val = 0.0f;
                if (m < mlim) {
                    const float* vp = v + ((size_t)(m0 + m) * 64 + j0 + k) * 3;
                    float x = vp[0], y = vp[1], z = vp[2];
                    val = sqrtf(x * x + y * y + z * z);
                }
                s[OFF_FEAT + k * FEAT_PITCH + m] = val;
            }
        } else {
            // t invariants: 16 channels (trace, frob interleaved)
            const int c0 = (kc - 192) >> 1;
            for (int i = tid; i < MTILE * 16; i += NTHREADS) {
                int m = i >> 4, cc = i & 15;
                float tr = 0.0f, fb = 0.0f;
                if (m < mlim) {
                    const float* tp = t + ((size_t)(m0 + m) * 64 + c0 + cc) * 9;
                    float q0 = tp[0], q1 = tp[1], q2 = tp[2];
                    float q3 = tp[3], q4 = tp[4], q5 = tp[5];
                    float q6 = tp[6], q7 = tp[7], q8 = tp[8];
                    tr = q0 + q4 + q8;
                    fb = sqrtf(q0*q0 + q1*q1 + q2*q2 + q3*q3 + q4*q4 +
                               q5*q5 + q6*q6 + q7*q7 + q8*q8);
                }
                s[OFF_FEAT + (2 * cc)     * FEAT_PITCH + m] = tr;
                s[OFF_FEAT + (2 * cc + 1) * FEAT_PITCH + m] = fb;
            }
        }
        // ---- stage W1 chunk [32][160] ----
        for (int i = tid; i < 32 * 160; i += NTHREADS)
            s[OFF_W1S + i] = W1[(size_t)kc * 160 + i];
        __syncthreads();

#pragma unroll 4
        for (int k = 0; k < 32; ++k) {
            const float4 a4 = *reinterpret_cast<const float4*>(
                &s[OFF_FEAT + k * FEAT_PITCH + tm]);
            float av[4] = {a4.x, a4.y, a4.z, a4.w};
            float bv[10];
#pragma unroll
            for (int j = 0; j < 10; j += 2) {
                const float2 bb = *reinterpret_cast<const float2*>(
                    &s[OFF_W1S + k * 160 + tn + j]);
                bv[j] = bb.x; bv[j + 1] = bb.y;
            }
#pragma unroll
            for (int i = 0; i < 4; ++i)
#pragma unroll
                for (int j = 0; j < 10; ++j)
                    acc[i][j] = fmaf(av[i], bv[j], acc[i][j]);
        }
        __syncthreads();
    }

    // bias + SiLU, write hT (overlays feat/W1 regions — barrier above protects)
#pragma unroll
    for (int j = 0; j < 10; ++j) {
        const float bj = b1[tn + j];
#pragma unroll
        for (int i = 0; i < 4; ++i) {
            float x  = acc[i][j] + bj;
            float sg = 1.0f / (1.0f + expf(-x));
            s[OFF_HT + (tn + j) * FEAT_PITCH + tm + i] = x * sg;
        }
    }
    __syncthreads();

    // ======================= GEMM2: [64,160] @ [160,64] =====================
    // W2 read via LDG: 16 threads share each 16B -> L1 broadcast.
    const int tn2 = (tid >> 4) * 4;
    float acc2[4][4];
#pragma unroll
    for (int i = 0; i < 4; ++i)
#pragma unroll
        for (int j = 0; j < 4; ++j) acc2[i][j] = 0.0f;

#pragma unroll 4
    for (int k = 0; k < 160; ++k) {
        const float4 a4 = *reinterpret_cast<const float4*>(
            &s[OFF_HT + k * FEAT_PITCH + tm]);
        const float4 b4 = *reinterpret_cast<const float4*>(
            &W2[(size_t)k * 64 + tn2]);
        float av[4] = {a4.x, a4.y, a4.z, a4.w};
        float bv[4] = {b4.x, b4.y, b4.z, b4.w};
#pragma unroll
        for (int i = 0; i < 4; ++i)
#pragma unroll
            for (int j = 0; j < 4; ++j)
                acc2[i][j] = fmaf(av[i], bv[j], acc2[i][j]);
    }
    __syncthreads();   // all reads of hT done; alpha overlays it

    // alphas -> smem
#pragma unroll
    for (int j = 0; j < 4; ++j) {
        const float bj = b2[tn2 + j];
#pragma unroll
        for (int i = 0; i < 4; ++i)
            s[OFF_ALPHA + (tm + i) * 65 + tn2 + j] = acc2[i][j] + bj;
    }
    __syncthreads();

    // ================ epilogue: gated sum, symmetrize, rotate ===============
    const int node = tid >> 2;   // 0..63
    const int jj   = tid & 3;    // 16 channels each
    float g[9];
#pragma unroll
    for (int k = 0; k < 9; ++k) g[k] = 0.0f;

    if (node < mlim) {
        const float4* tp4 = reinterpret_cast<const float4*>(
            t + ((size_t)(m0 + node) * 64 + jj * 16) * 9);
        const float* ap = &s[OFF_ALPHA + node * 65 + jj * 16];
#pragma unroll
        for (int cb = 0; cb < 4; ++cb) {
            float4 q[9];
#pragma unroll
            for (int u = 0; u < 9; ++u) q[u] = tp4[cb * 9 + u];
            const float* f = reinterpret_cast<const float*>(q);
            float al[4];
#pragma unroll
            for (int c = 0; c < 4; ++c) al[c] = ap[cb * 4 + c];
#pragma unroll
            for (int c = 0; c < 4; ++c)
#pragma unroll
                for (int k = 0; k < 9; ++k)
                    g[k] = fmaf(al[c], f[c * 9 + k], g[k]);
        }
    }

    // reduce across the 4 lanes of this node
#pragma unroll
    for (int k = 0; k < 9; ++k) {
        g[k] += __shfl_xor_sync(0xFFFFFFFFu, g[k], 1);
        g[k] += __shfl_xor_sync(0xFFFFFFFFu, g[k], 2);
    }

    if (jj == 0) {
        float G[9];
        if (node < mlim) {
            float S[9];
#pragma unroll
            for (int a = 0; a < 3; ++a)
#pragma unroll
                for (int b = 0; b < 3; ++b)
                    S[a * 3 + b] = 0.5f * (g[a * 3 + b] + g[b * 3 + a]);
            const float* rp = frames + (size_t)(m0 + node) * 9;
            float R[9];
#pragma unroll
            for (int k = 0; k < 9; ++k) R[k] = rp[k];
            float P[9];
#pragma unroll
            for (int a = 0; a < 3; ++a)
#pragma unroll
                for (int c = 0; c < 3; ++c)
                    P[a * 3 + c] = R[a * 3 + 0] * S[0 * 3 + c]
                                 + R[a * 3 + 1] * S[1 * 3 + c]
                                 + R[a * 3 + 2] * S[2 * 3 + c];
#pragma unroll
            for (int a = 0; a < 3; ++a)
#pragma unroll
                for (int d = 0; d < 3; ++d)
                    G[a * 3 + d] = P[a * 3 + 0] * R[d * 3 + 0]
                                 + P[a * 3 + 1] * R[d * 3 + 1]
                                 + P[a * 3 + 2] * R[d * 3 + 2];
        } else {
#pragma unroll
            for (int k = 0; k < 9; ++k) G[k] = 0.0f;
        }
#pragma unroll
        for (int k = 0; k < 9; ++k) s[OFF_GS + node * 9 + k] = G[k];
    }
    __syncthreads();

    // ============ sorted-run segment sum: few atomics per block =============
    if (tid < 9) {
        int cur = batch[m0];
        float run = 0.0f;
        for (int n = 0; n < mlim; ++n) {
            int b = batch[m0 + n];
            if (b != cur) {
                if ((unsigned)cur < (unsigned)num_graphs)
                    atomicAdd(&out[(size_t)cur * 9 + tid], run);
                run = 0.0f;
                cur = b;
            }
            run += s[OFF_GS + n * 9 + tid];
        }
        if ((unsigned)cur < (unsigned)num_graphs)
            atomicAdd(&out[(size_t)cur * 9 + tid], run);
    }
}

extern "C" void kernel_launch(void* const* d_in, const int* in_sizes, int n_in,
                              void* d_out, int out_size)
{
    const float* h      = (const float*)d_in[0];
    const float* v      = (const float*)d_in[1];
    const float* t      = (const float*)d_in[2];
    const float* frames = (const float*)d_in[3];
    const int*   batch  = (const int*)d_in[4];
    const float* W1     = (const float*)d_in[5];
    const float* b1     = (const float*)d_in[6];
    const float* W2     = (const float*)d_in[7];
    const float* b2     = (const float*)d_in[8];
    float* out = (float*)d_out;

    const int N = in_sizes[0] / 128;          // h is [N,128]
    const int num_graphs = out_size / 9;

    cudaMemsetAsync(d_out, 0, (size_t)out_size * sizeof(float));

    cudaFuncSetAttribute(tensor_message_fused,
                         cudaFuncAttributeMaxDynamicSharedMemorySize, SMEM_BYTES);

    const int grid = (N + MTILE - 1) / MTILE;
    tensor_message_fused<<<grid, NTHREADS, SMEM_BYTES>>>(
        h, v, t, frames, batch, W1, b1, W2, b2, out, N, num_graphs);
}

// round 3
// speedup vs baseline: 1.8951x; 1.0290x over previous
#include <cuda_runtime.h>
#include <math.h>

// ---------------------------------------------------------------------------
// Round 3: packed fp32 (fma.rn.f32x2 / FFMA2) in both GEMMs.
// FFMA-3reg issues at rt_SMSP=2 on sm_103a -> 2 warp-instr/cyc/SM ceiling was
// the binder (85% of it). FFMA2 does 2 FMAs/instr -> halves GEMM issue count.
// ---------------------------------------------------------------------------

#define MTILE 64
#define NTHREADS 256
#define FEAT_PITCH 68

// smem float offsets (regions overlaid across phases, separated by barriers)
#define OFF_FEAT   0        // feat chunk [32][68]   -> 2176 floats
#define OFF_W1S    2176     // W1 chunk  [32][160]  -> 5120 floats (end 7296)
#define OFF_HT     0        // hT [160][68]         -> 10880 floats (phase 2)
#define OFF_ALPHA  0        // alpha [64][65]       -> 4160 floats (phase 3)
#define OFF_GS     4352     // Gs [64][9]           -> 576 floats  (phase 4)
#define SMEM_FLOATS 10880
#define SMEM_BYTES  (SMEM_FLOATS * 4)

typedef unsigned long long ull;

__device__ __forceinline__ ull pk2(float x, float y) {
    ull r; asm("mov.b64 %0, {%1, %2};" : "=l"(r) : "f"(x), "f"(y)); return r;
}
__device__ __forceinline__ void upk2(float& x, float& y, ull v) {
    asm("mov.b64 {%0, %1}, %2;" : "=f"(x), "=f"(y) : "l"(v));
}
__device__ __forceinline__ void fma2(ull& d, ull a, ull b) {
    asm("fma.rn.f32x2 %0, %1, %2, %0;" : "+l"(d) : "l"(a), "l"(b));
}

__global__ void __launch_bounds__(NTHREADS, 3)
tensor_message_fused(const float* __restrict__ h,
                     const float* __restrict__ v,
                     const float* __restrict__ t,
                     const float* __restrict__ frames,
                     const int* __restrict__ batch,
                     const float* __restrict__ W1,
                     const float* __restrict__ b1,
                     const float* __restrict__ W2,
                     const float* __restrict__ b2,
                     float* __restrict__ out,
                     int N, int num_graphs)
{
    extern __shared__ float s[];
    const int tid = threadIdx.x;
    const int m0  = blockIdx.x * MTILE;
    const int mlim = (N - m0 < MTILE) ? (N - m0) : MTILE;

    // ======================= GEMM1: [64,320] @ [320,160] ====================
    const int tm  = (tid & 15) * 4;    // 4 node-rows
    const int tn  = (tid >> 4) * 10;   // 10 hidden cols (5 packed pairs)

    ull accp[4][5];
#pragma unroll
    for (int i = 0; i < 4; ++i)
#pragma unroll
        for (int j = 0; j < 5; ++j) accp[i][j] = 0ULL;

    for (int kc = 0; kc < 320; kc += 32) {
        // ---- build feature chunk [32 k-rows][64 nodes] ----
        if (kc < 128) {
            for (int i = tid; i < MTILE * 32; i += NTHREADS) {
                int m = i >> 5, k = i & 31;
                float val = 0.0f;
                if (m < mlim) val = h[(size_t)(m0 + m) * 128 + kc + k];
                s[OFF_FEAT + k * FEAT_PITCH + m] = val;
            }
        } else if (kc < 192) {
            const int j0 = kc - 128;
            for (int i = tid; i < MTILE * 32; i += NTHREADS) {
                int m = i >> 5, k = i & 31;
                float val = 0.0f;
                if (m < mlim) {
                    const float* vp = v + ((size_t)(m0 + m) * 64 + j0 + k) * 3;
                    float x = vp[0], y = vp[1], z = vp[2];
                    val = sqrtf(x * x + y * y + z * z);
                }
                s[OFF_FEAT + k * FEAT_PITCH + m] = val;
            }
        } else {
            const int c0 = (kc - 192) >> 1;
            for (int i = tid; i < MTILE * 16; i += NTHREADS) {
                int m = i >> 4, cc = i & 15;
                float tr = 0.0f, fb = 0.0f;
                if (m < mlim) {
                    const float* tp = t + ((size_t)(m0 + m) * 64 + c0 + cc) * 9;
                    float q0 = tp[0], q1 = tp[1], q2 = tp[2];
                    float q3 = tp[3], q4 = tp[4], q5 = tp[5];
                    float q6 = tp[6], q7 = tp[7], q8 = tp[8];
                    tr = q0 + q4 + q8;
                    fb = sqrtf(q0*q0 + q1*q1 + q2*q2 + q3*q3 + q4*q4 +
                               q5*q5 + q6*q6 + q7*q7 + q8*q8);
                }
                s[OFF_FEAT + (2 * cc)     * FEAT_PITCH + m] = tr;
                s[OFF_FEAT + (2 * cc + 1) * FEAT_PITCH + m] = fb;
            }
        }
        // ---- stage W1 chunk [32][160] ----
        for (int i = tid; i < 32 * 160; i += NTHREADS)
            s[OFF_W1S + i] = W1[(size_t)kc * 160 + i];
        __syncthreads();

#pragma unroll 4
        for (int k = 0; k < 32; ++k) {
            const float4 a4 = *reinterpret_cast<const float4*>(
                &s[OFF_FEAT + k * FEAT_PITCH + tm]);
            ull avd[4];
            avd[0] = pk2(a4.x, a4.x);
            avd[1] = pk2(a4.y, a4.y);
            avd[2] = pk2(a4.z, a4.z);
            avd[3] = pk2(a4.w, a4.w);
            // W1 pairs are natural 8B words in smem (tn even)
            const ull* bp = reinterpret_cast<const ull*>(
                &s[OFF_W1S + k * 160 + tn]);
            ull bv2[5];
#pragma unroll
            for (int j = 0; j < 5; ++j) bv2[j] = bp[j];
#pragma unroll
            for (int i = 0; i < 4; ++i)
#pragma unroll
                for (int j = 0; j < 5; ++j)
                    fma2(accp[i][j], avd[i], bv2[j]);
        }
        __syncthreads();
    }

    // bias + SiLU, write hT (overlays feat/W1 regions — barrier above protects)
#pragma unroll
    for (int j2 = 0; j2 < 5; ++j2) {
        const float b_lo = b1[tn + 2 * j2];
        const float b_hi = b1[tn + 2 * j2 + 1];
#pragma unroll
        for (int i = 0; i < 4; ++i) {
            float lo, hi;
            upk2(lo, hi, accp[i][j2]);
            float x0 = lo + b_lo, x1 = hi + b_hi;
            float s0 = x0 / (1.0f + __expf(-x0));
            float s1 = x1 / (1.0f + __expf(-x1));
            s[OFF_HT + (tn + 2 * j2)     * FEAT_PITCH + tm + i] = s0;
            s[OFF_HT + (tn + 2 * j2 + 1) * FEAT_PITCH + tm + i] = s1;
        }
    }
    __syncthreads();

    // ======================= GEMM2: [64,160] @ [160,64] =====================
    const int tn2 = (tid >> 4) * 4;    // 4 cols = 2 packed pairs
    ull acc2p[4][2];
#pragma unroll
    for (int i = 0; i < 4; ++i) { acc2p[i][0] = 0ULL; acc2p[i][1] = 0ULL; }

#pragma unroll 4
    for (int k = 0; k < 160; ++k) {
        const float4 a4 = *reinterpret_cast<const float4*>(
            &s[OFF_HT + k * FEAT_PITCH + tm]);
        const ulonglong2 b2v = *reinterpret_cast<const ulonglong2*>(
            &W2[(size_t)k * 64 + tn2]);
        ull avd[4];
        avd[0] = pk2(a4.x, a4.x);
        avd[1] = pk2(a4.y, a4.y);
        avd[2] = pk2(a4.z, a4.z);
        avd[3] = pk2(a4.w, a4.w);
#pragma unroll
        for (int i = 0; i < 4; ++i) {
            fma2(acc2p[i][0], avd[i], b2v.x);
            fma2(acc2p[i][1], avd[i], b2v.y);
        }
    }
    __syncthreads();   // all reads of hT done; alpha overlays it

    // alphas -> smem
    {
        const float b_0 = b2[tn2 + 0], b_1 = b2[tn2 + 1];
        const float b_2 = b2[tn2 + 2], b_3 = b2[tn2 + 3];
#pragma unroll
        for (int i = 0; i < 4; ++i) {
            float a0, a1, a2, a3;
            upk2(a0, a1, acc2p[i][0]);
            upk2(a2, a3, acc2p[i][1]);
            float* ap = &s[OFF_ALPHA + (tm + i) * 65 + tn2];
            ap[0] = a0 + b_0;
            ap[1] = a1 + b_1;
            ap[2] = a2 + b_2;
            ap[3] = a3 + b_3;
        }
    }
    __syncthreads();

    // ================ epilogue: gated sum, symmetrize, rotate ===============
    const int node = tid >> 2;   // 0..63
    const int jj   = tid & 3;    // 16 channels each
    float g[9];
#pragma unroll
    for (int k = 0; k < 9; ++k) g[k] = 0.0f;

    if (node < mlim) {
        const float4* tp4 = reinterpret_cast<const float4*>(
            t + ((size_t)(m0 + node) * 64 + jj * 16) * 9);
        const float* ap = &s[OFF_ALPHA + node * 65 + jj * 16];
#pragma unroll
        for (int cb = 0; cb < 4; ++cb) {
            float4 q[9];
#pragma unroll
            for (int u = 0; u < 9; ++u) q[u] = tp4[cb * 9 + u];
            const float* f = reinterpret_cast<const float*>(q);
            float al[4];
#pragma unroll
            for (int c = 0; c < 4; ++c) al[c] = ap[cb * 4 + c];
#pragma unroll
            for (int c = 0; c < 4; ++c)
#pragma unroll
                for (int k = 0; k < 9; ++k)
                    g[k] = fmaf(al[c], f[c * 9 + k], g[k]);
        }
    }

    // reduce across the 4 lanes of this node
#pragma unroll
    for (int k = 0; k < 9; ++k) {
        g[k] += __shfl_xor_sync(0xFFFFFFFFu, g[k], 1);
        g[k] += __shfl_xor_sync(0xFFFFFFFFu, g[k], 2);
    }

    if (jj == 0) {
        float G[9];
        if (node < mlim) {
            float S[9];
#pragma unroll
            for (int a = 0; a < 3; ++a)
#pragma unroll
                for (int b = 0; b < 3; ++b)
                    S[a * 3 + b] = 0.5f * (g[a * 3 + b] + g[b * 3 + a]);
            const float* rp = frames + (size_t)(m0 + node) * 9;
            float R[9];
#pragma unroll
            for (int k = 0; k < 9; ++k) R[k] = rp[k];
            float P[9];
#pragma unroll
            for (int a = 0; a < 3; ++a)
#pragma unroll
                for (int c = 0; c < 3; ++c)
                    P[a * 3 + c] = R[a * 3 + 0] * S[0 * 3 + c]
                                 + R[a * 3 + 1] * S[1 * 3 + c]
                                 + R[a * 3 + 2] * S[2 * 3 + c];
#pragma unroll
            for (int a = 0; a < 3; ++a)
#pragma unroll
                for (int d = 0; d < 3; ++d)
                    G[a * 3 + d] = P[a * 3 + 0] * R[d * 3 + 0]
                                 + P[a * 3 + 1] * R[d * 3 + 1]
                                 + P[a * 3 + 2] * R[d * 3 + 2];
        } else {
#pragma unroll
            for (int k = 0; k < 9; ++k) G[k] = 0.0f;
        }
#pragma unroll
        for (int k = 0; k < 9; ++k) s[OFF_GS + node * 9 + k] = G[k];
    }
    __syncthreads();

    // ============ sorted-run segment sum: few atomics per block =============
    if (tid < 9) {
        int cur = batch[m0];
        float run = 0.0f;
        for (int n = 0; n < mlim; ++n) {
            int b = batch[m0 + n];
            if (b != cur) {
                if ((unsigned)cur < (unsigned)num_graphs)
                    atomicAdd(&out[(size_t)cur * 9 + tid], run);
                run = 0.0f;
                cur = b;
            }
            run += s[OFF_GS + n * 9 + tid];
        }
        if ((unsigned)cur < (unsigned)num_graphs)
            atomicAdd(&out[(size_t)cur * 9 + tid], run);
    }
}

extern "C" void kernel_launch(void* const* d_in, const int* in_sizes, int n_in,
                              void* d_out, int out_size)
{
    const float* h      = (const float*)d_in[0];
    const float* v      = (const float*)d_in[1];
    const float* t      = (const float*)d_in[2];
    const float* frames = (const float*)d_in[3];
    const int*   batch  = (const int*)d_in[4];
    const float* W1     = (const float*)d_in[5];
    const float* b1     = (const float*)d_in[6];
    const float* W2     = (const float*)d_in[7];
    const float* b2     = (const float*)d_in[8];
    float* out = (float*)d_out;

    const int N = in_sizes[0] / 128;          // h is [N,128]
    const int num_graphs = out_size / 9;

    cudaMemsetAsync(d_out, 0, (size_t)out_size * sizeof(float));

    cudaFuncSetAttribute(tensor_message_fused,
                         cudaFuncAttributeMaxDynamicSharedMemorySize, SMEM_BYTES);

    const int grid = (N + MTILE - 1) / MTILE;
    tensor_message_fused<<<grid, NTHREADS, SMEM_BYTES>>>(
        h, v, t, frames, batch, W1, b1, W2, b2, out, N, num_graphs);
}